// round 2
// baseline (speedup 1.0000x reference)
#include <cuda_runtime.h>

#define B   32
#define C   9
#define NA  65440
#define NA4 (NA / 4)            // 16360
#define BLOCK 256
#define GX  ((NA4 + BLOCK - 1) / BLOCK)   // 64
#define NBLK (GX * B)                     // 2048
#define SCALE_XY 10.0f
#define SCALE_WH 5.0f
#define ALPHA_SUM 8010.0f       // 10 + 8*1000

__device__ float g_focal[NBLK];
__device__ float g_reg[NBLK];
__device__ int   g_pos[NBLK];

__device__ __forceinline__ float warpReduceF(float v) {
    #pragma unroll
    for (int o = 16; o > 0; o >>= 1) v += __shfl_down_sync(0xffffffffu, v, o);
    return v;
}
__device__ __forceinline__ int warpReduceI(int v) {
    #pragma unroll
    for (int o = 16; o > 0; o >>= 1) v += __shfl_down_sync(0xffffffffu, v, o);
    return v;
}

__global__ void __launch_bounds__(BLOCK)
ssd_loss_main(const float* __restrict__ bbox_delta,
              const float* __restrict__ confs,
              const float* __restrict__ gt_bbox,
              const int*   __restrict__ gt_labels,
              const float* __restrict__ anchors) {
    const int b = blockIdx.y;
    const int v = blockIdx.x * BLOCK + threadIdx.x;   // vec4 index within NA4

    float focal_acc = 0.0f;
    float reg_acc   = 0.0f;
    int   pos_acc   = 0;

    if (v < NA4) {
        const int a = v * 4;

        // --- labels (int4) ---
        int4 lab4 = *reinterpret_cast<const int4*>(gt_labels + (size_t)b * NA + a);
        int labs[4] = {lab4.x, lab4.y, lab4.z, lab4.w};

        // --- classification: log-softmax over C=9 classes, focal loss ---
        float cf[C][4];
        const float* cbase = confs + (size_t)b * C * NA + a;
        #pragma unroll
        for (int c = 0; c < C; c++) {
            float4 t = *reinterpret_cast<const float4*>(cbase + (size_t)c * NA);
            cf[c][0] = t.x; cf[c][1] = t.y; cf[c][2] = t.z; cf[c][3] = t.w;
        }
        #pragma unroll
        for (int j = 0; j < 4; j++) {
            float m = cf[0][j];
            #pragma unroll
            for (int c = 1; c < C; c++) m = fmaxf(m, cf[c][j]);
            float s = 0.0f;
            float ct = cf[0][j];                 // logit at the target class
            #pragma unroll
            for (int c = 0; c < C; c++) {
                s += __expf(cf[c][j] - m);
                if (labs[j] == c) ct = cf[c][j]; // static-indexed SEL chain (no spill)
            }
            float lse    = m + __logf(s);
            float logp_t = ct - lse;
            float p_t    = __expf(logp_t);
            float om     = 1.0f - p_t;
            focal_acc += om * om * om * logp_t;
        }

        // --- regression: smooth-L1 on positive anchors ---
        float bd[4][4], an[4][4];
        const float* bbase = bbox_delta + (size_t)b * 4 * NA + a;
        #pragma unroll
        for (int c = 0; c < 4; c++) {
            float4 t = *reinterpret_cast<const float4*>(bbase + (size_t)c * NA);
            bd[c][0] = t.x; bd[c][1] = t.y; bd[c][2] = t.z; bd[c][3] = t.w;
        }
        #pragma unroll
        for (int c = 0; c < 4; c++) {
            float4 t = *reinterpret_cast<const float4*>(anchors + (size_t)c * NA + a);
            an[c][0] = t.x; an[c][1] = t.y; an[c][2] = t.z; an[c][3] = t.w;
        }
        const float4* gtb = reinterpret_cast<const float4*>(gt_bbox + ((size_t)b * NA + a) * 4);

        #pragma unroll
        for (int j = 0; j < 4; j++) {
            if (labs[j] > 0) {
                pos_acc++;
                float4 g = gtb[j];
                float inv_w = 1.0f / an[2][j];
                float inv_h = 1.0f / an[3][j];
                float gl0 = SCALE_XY * (g.x - an[0][j]) * inv_w;
                float gl1 = SCALE_XY * (g.y - an[1][j]) * inv_h;
                float gl2 = SCALE_WH * __logf(g.z * inv_w);
                float gl3 = SCALE_WH * __logf(g.w * inv_h);
                float d0 = bd[0][j] - gl0;
                float d1 = bd[1][j] - gl1;
                float d2 = bd[2][j] - gl2;
                float d3 = bd[3][j] - gl3;
                float ds[4] = {d0, d1, d2, d3};
                #pragma unroll
                for (int c = 0; c < 4; c++) {
                    float ad = fabsf(ds[c]);
                    reg_acc += (ad < 1.0f) ? 0.5f * ds[c] * ds[c] : ad - 0.5f;
                }
            }
        }
    }

    // --- block reduction (deterministic) ---
    __shared__ float sF[BLOCK / 32];
    __shared__ float sR[BLOCK / 32];
    __shared__ int   sP[BLOCK / 32];
    int lane = threadIdx.x & 31;
    int wid  = threadIdx.x >> 5;

    focal_acc = warpReduceF(focal_acc);
    reg_acc   = warpReduceF(reg_acc);
    pos_acc   = warpReduceI(pos_acc);
    if (lane == 0) { sF[wid] = focal_acc; sR[wid] = reg_acc; sP[wid] = pos_acc; }
    __syncthreads();
    if (wid == 0) {
        float f = (lane < BLOCK / 32) ? sF[lane] : 0.0f;
        float r = (lane < BLOCK / 32) ? sR[lane] : 0.0f;
        int   p = (lane < BLOCK / 32) ? sP[lane] : 0;
        f = warpReduceF(f);
        r = warpReduceF(r);
        p = warpReduceI(p);
        if (lane == 0) {
            int out = blockIdx.y * GX + blockIdx.x;
            g_focal[out] = f;
            g_reg[out]   = r;
            g_pos[out]   = p;
        }
    }
}

__global__ void __launch_bounds__(1024)
ssd_loss_final(float* __restrict__ out) {
    const int tid = threadIdx.x;
    float f = 0.0f, r = 0.0f;
    int   p = 0;
    #pragma unroll
    for (int i = tid; i < NBLK; i += 1024) {
        f += g_focal[i];
        r += g_reg[i];
        p += g_pos[i];
    }
    __shared__ float sF[32];
    __shared__ float sR[32];
    __shared__ int   sP[32];
    int lane = tid & 31, wid = tid >> 5;
    f = warpReduceF(f); r = warpReduceF(r); p = warpReduceI(p);
    if (lane == 0) { sF[wid] = f; sR[wid] = r; sP[wid] = p; }
    __syncthreads();
    if (wid == 0) {
        f = (lane < 32) ? sF[lane] : 0.0f;
        r = (lane < 32) ? sR[lane] : 0.0f;
        p = (lane < 32) ? sP[lane] : 0;
        f = warpReduceF(f); r = warpReduceF(r); p = warpReduceI(p);
        if (lane == 0) {
            float cls = -ALPHA_SUM * f / (float)((size_t)B * NA);
            out[0] = r / (float)p + cls;
        }
    }
}

extern "C" void kernel_launch(void* const* d_in, const int* in_sizes, int n_in,
                              void* d_out, int out_size) {
    const float* bbox_delta = (const float*)d_in[0];
    const float* confs      = (const float*)d_in[1];
    const float* gt_bbox    = (const float*)d_in[2];
    const int*   gt_labels  = (const int*)d_in[3];
    const float* anchors    = (const float*)d_in[4];

    dim3 grid(GX, B);
    ssd_loss_main<<<grid, BLOCK>>>(bbox_delta, confs, gt_bbox, gt_labels, anchors);
    ssd_loss_final<<<1, 1024>>>((float*)d_out);
}

// round 3
// speedup vs baseline: 1.1164x; 1.1164x over previous
#include <cuda_runtime.h>

#define B   32
#define C   9
#define NA  65440
#define NA4 (NA / 4)            // 16360
#define BLOCK 256
#define GX  ((NA4 + BLOCK - 1) / BLOCK)   // 64
#define NBLK (GX * B)                     // 2048
#define SCALE_XY 10.0f
#define SCALE_WH 5.0f
#define ALPHA_SUM 8010.0f       // 10 + 8*1000

__device__ float g_focal[NBLK];
__device__ float g_reg[NBLK];
__device__ int   g_pos[NBLK];
__device__ int   g_ticket;      // zero-initialized; last block resets -> replay-safe

__device__ __forceinline__ float warpReduceF(float v) {
    #pragma unroll
    for (int o = 16; o > 0; o >>= 1) v += __shfl_down_sync(0xffffffffu, v, o);
    return v;
}
__device__ __forceinline__ int warpReduceI(int v) {
    #pragma unroll
    for (int o = 16; o > 0; o >>= 1) v += __shfl_down_sync(0xffffffffu, v, o);
    return v;
}

__global__ void __launch_bounds__(BLOCK)
ssd_loss_fused(const float* __restrict__ bbox_delta,
               const float* __restrict__ confs,
               const float* __restrict__ gt_bbox,
               const int*   __restrict__ gt_labels,
               const float* __restrict__ anchors,
               float*       __restrict__ out) {
    const int b = blockIdx.y;
    const int v = blockIdx.x * BLOCK + threadIdx.x;   // vec4 index within NA4

    float focal_acc = 0.0f;
    float reg_acc   = 0.0f;
    int   pos_acc   = 0;

    if (v < NA4) {
        const int a = v * 4;

        // ============ ISSUE ALL LOADS FIRST (max MLP, latency exposed once) ============
        int4 lab4 = __ldcs(reinterpret_cast<const int4*>(gt_labels + (size_t)b * NA + a));

        float4 cf4[C];
        const float* cbase = confs + (size_t)b * C * NA + a;
        #pragma unroll
        for (int c = 0; c < C; c++)
            cf4[c] = __ldcs(reinterpret_cast<const float4*>(cbase + (size_t)c * NA));

        float4 bd4[4];
        const float* bbase = bbox_delta + (size_t)b * 4 * NA + a;
        #pragma unroll
        for (int c = 0; c < 4; c++)
            bd4[c] = __ldcs(reinterpret_cast<const float4*>(bbase + (size_t)c * NA));

        float4 an4[4];
        #pragma unroll
        for (int c = 0; c < 4; c++)
            an4[c] = __ldg(reinterpret_cast<const float4*>(anchors + (size_t)c * NA + a));

        float4 gt4[4];
        const float4* gtb = reinterpret_cast<const float4*>(gt_bbox + ((size_t)b * NA + a) * 4);
        #pragma unroll
        for (int j = 0; j < 4; j++)
            gt4[j] = __ldcs(gtb + j);

        // ============ COMPUTE ============
        int labs[4] = {lab4.x, lab4.y, lab4.z, lab4.w};
        float cf[C][4];
        #pragma unroll
        for (int c = 0; c < C; c++) {
            cf[c][0] = cf4[c].x; cf[c][1] = cf4[c].y; cf[c][2] = cf4[c].z; cf[c][3] = cf4[c].w;
        }
        float bd[4][4], an[4][4];
        #pragma unroll
        for (int c = 0; c < 4; c++) {
            bd[c][0] = bd4[c].x; bd[c][1] = bd4[c].y; bd[c][2] = bd4[c].z; bd[c][3] = bd4[c].w;
            an[c][0] = an4[c].x; an[c][1] = an4[c].y; an[c][2] = an4[c].z; an[c][3] = an4[c].w;
        }

        // --- classification: log-softmax over C=9 classes, focal loss ---
        #pragma unroll
        for (int j = 0; j < 4; j++) {
            float m = cf[0][j];
            #pragma unroll
            for (int c = 1; c < C; c++) m = fmaxf(m, cf[c][j]);
            float s = 0.0f;
            float ct = cf[0][j];                 // logit at target class
            #pragma unroll
            for (int c = 0; c < C; c++) {
                s += __expf(cf[c][j] - m);
                if (labs[j] == c) ct = cf[c][j]; // static-indexed SEL chain
            }
            float lse    = m + __logf(s);
            float logp_t = ct - lse;
            float p_t    = __expf(logp_t);
            float om     = 1.0f - p_t;
            focal_acc += om * om * om * logp_t;
        }

        // --- regression: smooth-L1 on positive anchors ---
        #pragma unroll
        for (int j = 0; j < 4; j++) {
            if (labs[j] > 0) {
                pos_acc++;
                float4 g = gt4[j];
                float inv_w = 1.0f / an[2][j];
                float inv_h = 1.0f / an[3][j];
                float gl0 = SCALE_XY * (g.x - an[0][j]) * inv_w;
                float gl1 = SCALE_XY * (g.y - an[1][j]) * inv_h;
                float gl2 = SCALE_WH * __logf(g.z * inv_w);
                float gl3 = SCALE_WH * __logf(g.w * inv_h);
                float ds[4] = {bd[0][j] - gl0, bd[1][j] - gl1,
                               bd[2][j] - gl2, bd[3][j] - gl3};
                #pragma unroll
                for (int c = 0; c < 4; c++) {
                    float ad = fabsf(ds[c]);
                    reg_acc += (ad < 1.0f) ? 0.5f * ds[c] * ds[c] : ad - 0.5f;
                }
            }
        }
    }

    // ============ block reduction (deterministic) ============
    __shared__ float sF[BLOCK / 32];
    __shared__ float sR[BLOCK / 32];
    __shared__ int   sP[BLOCK / 32];
    __shared__ int   sLast;
    int lane = threadIdx.x & 31;
    int wid  = threadIdx.x >> 5;

    focal_acc = warpReduceF(focal_acc);
    reg_acc   = warpReduceF(reg_acc);
    pos_acc   = warpReduceI(pos_acc);
    if (lane == 0) { sF[wid] = focal_acc; sR[wid] = reg_acc; sP[wid] = pos_acc; }
    __syncthreads();
    if (wid == 0) {
        float f = (lane < BLOCK / 32) ? sF[lane] : 0.0f;
        float r = (lane < BLOCK / 32) ? sR[lane] : 0.0f;
        int   p = (lane < BLOCK / 32) ? sP[lane] : 0;
        f = warpReduceF(f);
        r = warpReduceF(r);
        p = warpReduceI(p);
        if (lane == 0) {
            int outIdx = blockIdx.y * GX + blockIdx.x;
            g_focal[outIdx] = f;
            g_reg[outIdx]   = r;
            g_pos[outIdx]   = p;
            __threadfence();
            int t = atomicAdd(&g_ticket, 1);
            sLast = (t == NBLK - 1) ? 1 : 0;
        }
    }
    __syncthreads();

    // ============ last block folds the partials (fused epilogue) ============
    if (sLast) {
        float f = 0.0f, r = 0.0f;
        int   p = 0;
        #pragma unroll
        for (int i = threadIdx.x; i < NBLK; i += BLOCK) {
            f += g_focal[i];
            r += g_reg[i];
            p += g_pos[i];
        }
        f = warpReduceF(f); r = warpReduceF(r); p = warpReduceI(p);
        if (lane == 0) { sF[wid] = f; sR[wid] = r; sP[wid] = p; }
        __syncthreads();
        if (wid == 0) {
            f = (lane < BLOCK / 32) ? sF[lane] : 0.0f;
            r = (lane < BLOCK / 32) ? sR[lane] : 0.0f;
            p = (lane < BLOCK / 32) ? sP[lane] : 0;
            f = warpReduceF(f); r = warpReduceF(r); p = warpReduceI(p);
            if (lane == 0) {
                float cls = -ALPHA_SUM * f / (float)((size_t)B * NA);
                out[0] = r / (float)p + cls;
                g_ticket = 0;   // reset for next graph replay
            }
        }
    }
}

extern "C" void kernel_launch(void* const* d_in, const int* in_sizes, int n_in,
                              void* d_out, int out_size) {
    const float* bbox_delta = (const float*)d_in[0];
    const float* confs      = (const float*)d_in[1];
    const float* gt_bbox    = (const float*)d_in[2];
    const int*   gt_labels  = (const int*)d_in[3];
    const float* anchors    = (const float*)d_in[4];

    dim3 grid(GX, B);
    ssd_loss_fused<<<grid, BLOCK>>>(bbox_delta, confs, gt_bbox, gt_labels, anchors,
                                    (float*)d_out);
}